// round 14
// baseline (speedup 1.0000x reference)
#include <cuda_runtime.h>
#include <cuda_fp16.h>
#include <cstdint>

// TALayer = 9-tap conv, tap offsets d_j = 16*(j/3)+(j%3)-17.
// GEMM: D[o,t] = sum_k W[o,k]*X[k,t], k=(j,c), K=576.
// fp16 m16n8k16. x pre-converted fp16 t-major (g_xt, fused with W prep).
// T_TILE=512 staged once, computed as two 256-t halves (fewer barriers).
// Double-buffered cp.async staging. 1 CTA/SM x 512 thr, warp 32o x 32t.

#define T_LEN   65536
#define TP      65600        // 32 pad + 65536 + 32 pad
#define NB      8
#define NO      64
#define NC      64
#define T_TILE  512
#define HALO    17
#define XROWS   546          // T_TILE + 2*HALO
#define XPW     36           // words per smem x row (144B; 4 mod 32 -> LDS.32 bank-clean)
#define NCHUNK  36
#define GRID    148
#define NTILES  1024         // NB * T_LEN/T_TILE

// smem byte offsets
#define WFOFF   0
#define WFBYTES (NCHUNK*4*32*16)     // 73728
#define XS0     WFBYTES
#define XBUFB   (XROWS*XPW*4)        // 78624
#define SMTOT   (XS0 + 2*XBUFB)      // 230976

__device__ uint32_t g_wfrag[NCHUNK*4*32*4];
// x fp16, [b][t+32][c], rows of 128B, pads zeroed.
__device__ __align__(16) __half g_xt[(size_t)NB * TP * NC];

__device__ __forceinline__ uint32_t packh2(float lo, float hi) {
    __half2 h = __floats2half2_rn(lo, hi);
    return *(uint32_t*)&h;
}

// Fused prep: transpose+convert x, and (first 18 blocks) cook W fragments.
__global__ void prep_all(const float* __restrict__ x, const float* __restrict__ w) {
    int tid = threadIdx.x;

    if (blockIdx.x < 18) {
        int i = blockIdx.x * 256 + tid;
        if (i < NCHUNK * 128) {
            int q = i >> 7, rr = i & 127, mt = rr >> 5, lane = rr & 31;
            int j = q >> 2, cq = q & 3;
            int o0 = mt * 16 + (lane >> 2);
            int c0 = cq * 16 + (lane & 3) * 2;
            uint4 u;
            u.x = packh2(w[o0*576 + c0*9 + j],        w[o0*576 + (c0+1)*9 + j]);
            u.y = packh2(w[(o0+8)*576 + c0*9 + j],    w[(o0+8)*576 + (c0+1)*9 + j]);
            u.z = packh2(w[o0*576 + (c0+8)*9 + j],    w[o0*576 + (c0+9)*9 + j]);
            u.w = packh2(w[(o0+8)*576 + (c0+8)*9 + j],w[(o0+8)*576 + (c0+9)*9 + j]);
            ((uint4*)g_wfrag)[q * 128 + mt * 32 + lane] = u;
        }
    }

    __shared__ __half tile[256][66];
    int b  = blockIdx.x >> 8;
    int tt = blockIdx.x & 255;
    int t0 = tt << 8;
    uint32_t* dst = (uint32_t*)g_xt;

    if (tt == 0) {          // zero front pad rows [0,32)
        for (int i = tid; i < 32 * 32; i += 256)
            dst[((size_t)b*TP + (i >> 5))*32 + (i & 31)] = 0;
    } else if (tt == 255) { // zero back pad rows [TP-32, TP)
        for (int i = tid; i < 32 * 32; i += 256)
            dst[((size_t)b*TP + TP - 32 + (i >> 5))*32 + (i & 31)] = 0;
    }

#pragma unroll 8
    for (int c = 0; c < 64; ++c)
        tile[tid][c] = __float2half_rn(x[((size_t)(b*64 + c))*T_LEN + t0 + tid]);
    __syncthreads();
#pragma unroll 8
    for (int it = 0; it < 32; ++it) {
        int idx = it * 256 + tid;
        int i = idx >> 5, wd = idx & 31;
        __half2 h2;
        h2.x = tile[i][2*wd]; h2.y = tile[i][2*wd + 1];
        dst[((size_t)b*TP + 32 + t0 + i)*32 + wd] = *(uint32_t*)&h2;
    }
}

extern __shared__ char sm[];

__device__ __forceinline__ uint32_t s2u(const void* p) {
    uint32_t a;
    asm("{ .reg .u64 t; cvta.to.shared.u64 t, %1; cvt.u32.u64 %0, t; }"
        : "=r"(a) : "l"(p));
    return a;
}

#define CP_ASYNC16(d, s) \
    asm volatile("cp.async.cg.shared.global [%0], [%1], 16;" :: "r"(d), "l"(s))
#define CP_COMMIT() asm volatile("cp.async.commit_group;" ::: "memory")
#define CP_WAIT0()  asm volatile("cp.async.wait_group 0;" ::: "memory")

// Stage one 512-t tile's x rows (546 x 128B) into a smem buffer.
__device__ __forceinline__ void stage_x(int tile, uint32_t dstu, int tid) {
    const int b  = tile >> 7;
    const int t0 = (tile & 127) << 9;
    const char* src = (const char*)(g_xt + ((size_t)b*TP + 15 + t0) * 64);
#pragma unroll
    for (int s = 0; s < 9; ++s) {
        int idx = s * 512 + tid;
        if (idx < XROWS * 8) {
            int r = idx >> 3, ch = idx & 7;
            CP_ASYNC16(dstu + r*(XPW*4) + ch*16, src + (size_t)r*128 + ch*16);
        }
    }
}

__global__ __launch_bounds__(512, 1) void taconv_mma(
    const float* __restrict__ bias, float* __restrict__ out)
{
    const int tid  = threadIdx.x;
    const int wid  = tid >> 5;
    const int lane = tid & 31;
    const int og   = wid & 1;
    const int tg   = wid >> 1;

    {
        const uint4* gw = (const uint4*)g_wfrag;
        uint4* sw = (uint4*)(sm + WFOFF);
        for (int i = tid; i < NCHUNK * 128; i += 512) sw[i] = gw[i];
    }
    const int oA0 = og * 32 + (lane >> 2);
    float bv[2][2];
#pragma unroll
    for (int m = 0; m < 2; ++m) {
        bv[m][0] = __ldg(bias + oA0 + m * 16);
        bv[m][1] = __ldg(bias + oA0 + m * 16 + 8);
    }

    const uint32_t smb = s2u(sm);
    const int wrow = tg * 32 + (lane >> 2);   // B-frag t-row base within a half

    int tile = blockIdx.x;
    stage_x(tile, smb + XS0, tid);
    CP_COMMIT();

    int cur = 0;
    for (; tile < NTILES; tile += GRID) {
        CP_WAIT0();
        __syncthreads();

        // prefetch next tile into the other buffer (overlaps both halves)
        if (tile + GRID < NTILES)
            stage_x(tile + GRID, smb + XS0 + (cur ^ 1) * XBUFB, tid);
        CP_COMMIT();

        const uint32_t* xsbuf = (const uint32_t*)(sm + XS0 + cur * XBUFB);
        const uint4* wf_base = (const uint4*)(sm + WFOFF);
        const int b  = tile >> 7;
        const int t0 = (tile & 127) << 9;

#pragma unroll
        for (int half = 0; half < 2; ++half) {
            const uint32_t* xs = xsbuf + (half * 256) * XPW;

            // acc pre-loaded with bias
            float acc[2][4][4];
#pragma unroll
            for (int m = 0; m < 2; ++m)
#pragma unroll
                for (int n = 0; n < 4; ++n) {
                    acc[m][n][0] = bv[m][0]; acc[m][n][1] = bv[m][0];
                    acc[m][n][2] = bv[m][1]; acc[m][n][3] = bv[m][1];
                }

#pragma unroll
            for (int j = 0; j < 9; ++j) {
                const int offj = 16 * (j / 3) + (j % 3);
#pragma unroll
                for (int cq = 0; cq < 4; ++cq) {
                    const int q = j * 4 + cq;
                    uint4 wf[2];
#pragma unroll
                    for (int m = 0; m < 2; ++m)
                        wf[m] = wf_base[(q * 4 + og * 2 + m) * 32 + lane];

                    uint32_t bb[4][2];
                    const uint32_t* bp =
                        xs + (wrow + offj) * XPW + cq * 8 + (lane & 3);
#pragma unroll
                    for (int nt = 0; nt < 4; ++nt) {
                        bb[nt][0] = bp[nt * 8 * XPW];
                        bb[nt][1] = bp[nt * 8 * XPW + 4];
                    }
#pragma unroll
                    for (int m = 0; m < 2; ++m)
#pragma unroll
                        for (int nt = 0; nt < 4; ++nt)
                            asm volatile(
                                "mma.sync.aligned.m16n8k16.row.col.f32.f16.f16.f32 "
                                "{%0,%1,%2,%3}, {%4,%5,%6,%7}, {%8,%9}, {%0,%1,%2,%3};"
                                : "+f"(acc[m][nt][0]), "+f"(acc[m][nt][1]),
                                  "+f"(acc[m][nt][2]), "+f"(acc[m][nt][3])
                                : "r"(wf[m].x), "r"(wf[m].y),
                                  "r"(wf[m].z), "r"(wf[m].w),
                                  "r"(bb[nt][0]), "r"(bb[nt][1]));
                }
            }

            float* ob = out + (size_t)b * NO * T_LEN + t0 + half * 256
                            + tg * 32 + 2 * (lane & 3);
#pragma unroll
            for (int m = 0; m < 2; ++m) {
                int oA = oA0 + m * 16;
#pragma unroll
                for (int nt = 0; nt < 4; ++nt) {
                    *(float2*)(ob + (size_t)oA * T_LEN + nt * 8) =
                        make_float2(acc[m][nt][0], acc[m][nt][1]);
                    *(float2*)(ob + (size_t)(oA + 8) * T_LEN + nt * 8) =
                        make_float2(acc[m][nt][2], acc[m][nt][3]);
                }
            }
        }
        cur ^= 1;
    }
}

extern "C" void kernel_launch(void* const* d_in, const int* in_sizes, int n_in,
                              void* d_out, int out_size) {
    const float* x    = (const float*)d_in[0];
    const float* w    = (const float*)d_in[1];
    const float* bias = (const float*)d_in[2];
    float* out = (float*)d_out;

    prep_all<<<NB * 256, 256>>>(x, w);

    cudaFuncSetAttribute(taconv_mma,
                         cudaFuncAttributeMaxDynamicSharedMemorySize, SMTOT);
    taconv_mma<<<GRID, 512, SMTOT>>>(bias, out);
}

// round 15
// speedup vs baseline: 1.7940x; 1.7940x over previous
#include <cuda_runtime.h>
#include <cuda_fp16.h>
#include <cstdint>

// TALayer = 9-tap conv, tap offsets d_j = 16*(j/3)+(j%3)-17.
// GEMM: D[o,t] = sum_k W[o,k]*X[k,t], k=(j,c), K=576.
// Single fused kernel: cp.async f32 x tile -> in-smem fp16 transpose ->
// R9 mma mainloop (fp16 m16n8k16, warp 32o x 32t). W frags cooked in-kernel.
// 1 CTA/SM x 512 thr, T_TILE = 256.

#define T_LEN   65536
#define NB      8
#define NO      64
#define NC      64
#define T_TILE  256
#define HALO    17
#define XROWS   290          // fp16 rows per tile (T_TILE + 2*HALO)
#define XPW     36           // fp16 row stride in words (144B; LDS bank-clean)
#define FS      296          // f32 row stride in words (1184B, 74 x 16B chunks)
#define NCHUNK  36           // K=576/16
#define GRID    148
#define NTILES  2048

// smem byte offsets
#define WFOFF   0
#define WFBYTES (NCHUNK*4*32*16)     // 73728
#define FOFF    WFBYTES              // f32 stage buf: 64 * 1184 = 75776
#define XOFF    (FOFF + 64*FS*4)     // 149504
#define SMTOT   (XOFF + XROWS*XPW*4) // 191264

extern __shared__ char sm[];

__device__ __forceinline__ uint32_t s2u(const void* p) {
    uint32_t a;
    asm("{ .reg .u64 t; cvta.to.shared.u64 t, %1; cvt.u32.u64 %0, t; }"
        : "=r"(a) : "l"(p));
    return a;
}
__device__ __forceinline__ uint32_t packh2(float lo, float hi) {
    __half2 h = __floats2half2_rn(lo, hi);
    return *(uint32_t*)&h;
}

#define CP_ASYNC16(d, s) \
    asm volatile("cp.async.cg.shared.global [%0], [%1], 16;" :: "r"(d), "l"(s))
#define CP_COMMIT() asm volatile("cp.async.commit_group;" ::: "memory")
#define CP_WAIT0()  asm volatile("cp.async.wait_group 0;" ::: "memory")

// Stage one tile's raw f32 x rows: [c][t0-20 .. t0+276) -> smem f32 buffer.
// Edge chunks outside [0, T_LEN) are zero-filled with STS.
__device__ __forceinline__ void stage_f32(const float* __restrict__ x,
                                          int tile, uint32_t smb, int tid) {
    const int b  = tile >> 8;
    const int t0 = (tile & 255) << 8;
    const int ts0 = t0 - 20;
    const float* xb = x + (size_t)(b * 64) * T_LEN;
#pragma unroll
    for (int s = 0; s < 10; ++s) {
        int idx = s * 512 + tid;
        if (idx < 64 * 74) {
            int r = idx / 74, k = idx - r * 74;
            int ts = ts0 + 4 * k;
            uint32_t doff = (uint32_t)(FOFF + (r * FS + 4 * k) * 4);
            if (ts >= 0 && ts < T_LEN)
                CP_ASYNC16(smb + doff, xb + (size_t)r * T_LEN + ts);
            else
                *(uint4*)(sm + doff) = make_uint4(0, 0, 0, 0);
        }
    }
}

__global__ __launch_bounds__(512, 1) void taconv_mma(
    const float* __restrict__ x, const float* __restrict__ w,
    const float* __restrict__ bias, float* __restrict__ out)
{
    const int tid  = threadIdx.x;
    const int lane = tid & 31;
    const int wid  = tid >> 5;
    const int og   = wid & 1;
    const int tg   = wid >> 1;

    const uint32_t smb = s2u(sm);

    // ---- kick off first tile's f32 staging, then cook W frags (overlapped) ----
    int tile = blockIdx.x;
    stage_f32(x, tile, smb, tid);
    CP_COMMIT();

    {   // W fragments: exact m16n8k16 f16 A-frag layout, cooked from gmem
        uint4* sw = (uint4*)(sm + WFOFF);
#pragma unroll
        for (int e = tid; e < NCHUNK * 128; e += 512) {
            int q = e >> 7, rr = e & 127, mt = rr >> 5, ln = rr & 31;
            int j = q >> 2, cq = q & 3;
            int o0 = mt * 16 + (ln >> 2);
            int c0 = cq * 16 + (ln & 3) * 2;
            uint4 u;
            u.x = packh2(w[o0*576 + c0*9 + j],        w[o0*576 + (c0+1)*9 + j]);
            u.y = packh2(w[(o0+8)*576 + c0*9 + j],    w[(o0+8)*576 + (c0+1)*9 + j]);
            u.z = packh2(w[o0*576 + (c0+8)*9 + j],    w[o0*576 + (c0+9)*9 + j]);
            u.w = packh2(w[(o0+8)*576 + (c0+8)*9 + j],w[(o0+8)*576 + (c0+9)*9 + j]);
            sw[e] = u;
        }
    }
    const int oA0 = og * 32 + (lane >> 2);
    float bv[2][2];
#pragma unroll
    for (int m = 0; m < 2; ++m) {
        bv[m][0] = __ldg(bias + oA0 + m * 16);
        bv[m][1] = __ldg(bias + oA0 + m * 16 + 8);
    }

    const int wrow = tg * 32 + (lane >> 2);   // B-frag t-row base (pre-shift)

    for (; tile < NTILES; tile += GRID) {
        CP_WAIT0();
        __syncthreads();          // f32 ready; prev compute done (fp16 reusable)

        // ---- convert f32 [c][i+3] -> fp16 [i][c] (bank-clean both sides) ----
        {
            const float* fb = (const float*)(sm + FOFF);
#pragma unroll
            for (int u = tid; u < 8 * XROWS; u += 512) {
                int wblk = u / XROWS, i = u - wblk * XROWS;
                const float* src = fb + (8 * wblk) * FS + i + 3;
                uint32_t h0 = packh2(src[0],      src[FS]);
                uint32_t h1 = packh2(src[2*FS],   src[3*FS]);
                uint32_t h2 = packh2(src[4*FS],   src[5*FS]);
                uint32_t h3 = packh2(src[6*FS],   src[7*FS]);
                *(uint4*)(sm + XOFF + i * (XPW*4) + wblk * 16) =
                    make_uint4(h0, h1, h2, h3);
            }
        }
        __syncthreads();          // fp16 ready; f32 buffer free

        // ---- prefetch next tile's f32 (overlaps compute) ----
        if (tile + GRID < NTILES)
            stage_f32(x, tile + GRID, smb, tid);
        CP_COMMIT();

        // ---- mainloop (R9): 36 K-chunks, 8 mma each ----
        const uint32_t* xs = (const uint32_t*)(sm + XOFF);
        const uint4* wf_base = (const uint4*)(sm + WFOFF);

        float acc[2][4][4];
#pragma unroll
        for (int m = 0; m < 2; ++m)
#pragma unroll
            for (int n = 0; n < 4; ++n) {
                acc[m][n][0] = bv[m][0]; acc[m][n][1] = bv[m][0];
                acc[m][n][2] = bv[m][1]; acc[m][n][3] = bv[m][1];
            }

#pragma unroll
        for (int j = 0; j < 9; ++j) {
            const int offj = 16 * (j / 3) + (j % 3);
#pragma unroll
            for (int cq = 0; cq < 4; ++cq) {
                const int q = j * 4 + cq;
                uint4 wf[2];
#pragma unroll
                for (int m = 0; m < 2; ++m)
                    wf[m] = wf_base[(q * 4 + og * 2 + m) * 32 + lane];

                uint32_t bb[4][2];
                const uint32_t* bp =
                    xs + (wrow + offj) * XPW + cq * 8 + (lane & 3);
#pragma unroll
                for (int nt = 0; nt < 4; ++nt) {
                    bb[nt][0] = bp[nt * 8 * XPW];
                    bb[nt][1] = bp[nt * 8 * XPW + 4];
                }
#pragma unroll
                for (int m = 0; m < 2; ++m)
#pragma unroll
                    for (int nt = 0; nt < 4; ++nt)
                        asm volatile(
                            "mma.sync.aligned.m16n8k16.row.col.f32.f16.f16.f32 "
                            "{%0,%1,%2,%3}, {%4,%5,%6,%7}, {%8,%9}, {%0,%1,%2,%3};"
                            : "+f"(acc[m][nt][0]), "+f"(acc[m][nt][1]),
                              "+f"(acc[m][nt][2]), "+f"(acc[m][nt][3])
                            : "r"(wf[m].x), "r"(wf[m].y),
                              "r"(wf[m].z), "r"(wf[m].w),
                              "r"(bb[nt][0]), "r"(bb[nt][1]));
            }
        }

        // ---- epilogue: pure stores (bias already in acc) ----
        const int b  = tile >> 8;
        const int t0 = (tile & 255) << 8;
        float* ob = out + (size_t)b * NO * T_LEN + t0 + tg * 32 + 2 * (lane & 3);
#pragma unroll
        for (int m = 0; m < 2; ++m) {
            int oA = oA0 + m * 16;
#pragma unroll
            for (int nt = 0; nt < 4; ++nt) {
                *(float2*)(ob + (size_t)oA * T_LEN + nt * 8) =
                    make_float2(acc[m][nt][0], acc[m][nt][1]);
                *(float2*)(ob + (size_t)(oA + 8) * T_LEN + nt * 8) =
                    make_float2(acc[m][nt][2], acc[m][nt][3]);
            }
        }
    }
}

extern "C" void kernel_launch(void* const* d_in, const int* in_sizes, int n_in,
                              void* d_out, int out_size) {
    const float* x    = (const float*)d_in[0];
    const float* w    = (const float*)d_in[1];
    const float* bias = (const float*)d_in[2];
    float* out = (float*)d_out;

    cudaFuncSetAttribute(taconv_mma,
                         cudaFuncAttributeMaxDynamicSharedMemorySize, SMTOT);
    taconv_mma<<<GRID, 512, SMTOT>>>(x, w, bias, out);
}